// round 11
// baseline (speedup 1.0000x reference)
#include <cuda_runtime.h>

#define OBS_DIM   256
#define HID_DIM   512
#define ACT_DIM   18
#define BATCH     1024
#define ETA       0.01f
#define LAMBDA    0.95f

__device__ __forceinline__ float tanh_approx(float x) {
    float r;
    asm("tanh.approx.f32 %0, %1;" : "=f"(r) : "f"(x));
    return r;
}

// Fused MPN step + Hebbian update + q-head, dual-chain variant: each warp
// processes the same h row for TWO batches as fully independent chains.
// 4 front-batched M float4 loads put 2KB/warp in flight (2x R8's MLP); the
// two allreduce/tanh chains interleave so shuffle latency of one hides under
// the other. Epilogue barrier split arrive/sync; warp 0 emits 36 REDs/block
// reusing one Wq load for both batches.
__global__ __launch_bounds__(256) void mpn_step_kernel(
    const float* __restrict__ obs,
    const float* __restrict__ M,
    const float* __restrict__ W,
    const float* __restrict__ bh,
    const float* __restrict__ Wq,
    const float* __restrict__ bq,
    float* __restrict__ newM,
    float* __restrict__ q)
{
    __shared__ float hsh[2][8];         // hv per (batch, warp)

    const int b0    = blockIdx.x * 2;   // batch-major: W stays L1-hot per wave
    const int hbase = blockIdx.y * 8;
    const int tid   = threadIdx.x;
    const int warp  = tid >> 5;
    const int lane  = tid & 31;
    const int h     = hbase + warp;

    const size_t bstride = (size_t)HID_DIM * OBS_DIM / 4;   // float4 units
    const float4* Ma = reinterpret_cast<const float4*>(M)
                     + ((size_t)b0 * HID_DIM + h) * (OBS_DIM / 4);
    const float4* Mb = Ma + bstride;
    const float4* xa = reinterpret_cast<const float4*>(obs + (size_t)b0 * OBS_DIM);
    const float4* xb = xa + OBS_DIM / 4;
    const float4* wp = reinterpret_cast<const float4*>(W + (size_t)h * OBS_DIM);

    // Front-batch all streaming loads: 4 independent 512B/warp M accesses.
    const float4 ma0 = __ldcs(Ma + lane);
    const float4 ma1 = __ldcs(Ma + lane + 32);
    const float4 mb0 = __ldcs(Mb + lane);
    const float4 mb1 = __ldcs(Mb + lane + 32);
    const float4 w0  = __ldg(wp + lane);
    const float4 w1  = __ldg(wp + lane + 32);
    const float4 xa0 = __ldg(xa + lane);
    const float4 xa1 = __ldg(xa + lane + 32);
    const float4 xb0 = __ldg(xb + lane);
    const float4 xb1 = __ldg(xb + lane + 32);

    // Two independent dot products: sum_o W*x*(1+M)
    float accA =
        w0.x * xa0.x * (1.0f + ma0.x) + w0.y * xa0.y * (1.0f + ma0.y) +
        w0.z * xa0.z * (1.0f + ma0.z) + w0.w * xa0.w * (1.0f + ma0.w) +
        w1.x * xa1.x * (1.0f + ma1.x) + w1.y * xa1.y * (1.0f + ma1.y) +
        w1.z * xa1.z * (1.0f + ma1.z) + w1.w * xa1.w * (1.0f + ma1.w);
    float accB =
        w0.x * xb0.x * (1.0f + mb0.x) + w0.y * xb0.y * (1.0f + mb0.y) +
        w0.z * xb0.z * (1.0f + mb0.z) + w0.w * xb0.w * (1.0f + mb0.w) +
        w1.x * xb1.x * (1.0f + mb1.x) + w1.y * xb1.y * (1.0f + mb1.y) +
        w1.z * xb1.z * (1.0f + mb1.z) + w1.w * xb1.w * (1.0f + mb1.w);

    // Interleaved allreduces: chain B's shuffles hide chain A's latency.
    #pragma unroll
    for (int o = 16; o; o >>= 1) {
        accA += __shfl_xor_sync(0xffffffffu, accA, o);
        accB += __shfl_xor_sync(0xffffffffu, accB, o);
    }

    const float bias = __ldg(bh + h);
    const float hvA  = tanh_approx(accA + bias);
    const float hvB  = tanh_approx(accB + bias);
    const float ehA  = ETA * hvA;
    const float ehB  = ETA * hvB;

    float4* Oa = reinterpret_cast<float4*>(newM)
               + ((size_t)b0 * HID_DIM + h) * (OBS_DIM / 4);
    float4* Ob = Oa + bstride;

    float4 n;
    n.x = LAMBDA * ma0.x + ehA * xa0.x;  n.y = LAMBDA * ma0.y + ehA * xa0.y;
    n.z = LAMBDA * ma0.z + ehA * xa0.z;  n.w = LAMBDA * ma0.w + ehA * xa0.w;
    __stcs(Oa + lane, n);
    n.x = LAMBDA * ma1.x + ehA * xa1.x;  n.y = LAMBDA * ma1.y + ehA * xa1.y;
    n.z = LAMBDA * ma1.z + ehA * xa1.z;  n.w = LAMBDA * ma1.w + ehA * xa1.w;
    __stcs(Oa + lane + 32, n);
    n.x = LAMBDA * mb0.x + ehB * xb0.x;  n.y = LAMBDA * mb0.y + ehB * xb0.y;
    n.z = LAMBDA * mb0.z + ehB * xb0.z;  n.w = LAMBDA * mb0.w + ehB * xb0.w;
    __stcs(Ob + lane, n);
    n.x = LAMBDA * mb1.x + ehB * xb1.x;  n.y = LAMBDA * mb1.y + ehB * xb1.y;
    n.z = LAMBDA * mb1.z + ehB * xb1.z;  n.w = LAMBDA * mb1.w + ehB * xb1.w;
    __stcs(Ob + lane + 32, n);

    if (lane == 0) { hsh[0][warp] = hvA; hsh[1][warp] = hvB; }

    if (warp != 0) {
        // Producers: signal and retire. No blocking wait.
        asm volatile("bar.arrive 1, 256;");
        return;
    }
    asm volatile("bar.sync 1, 256;");

    // q-head epilogue: warp 0, one Wq load serves both batches. 36 REDs/block.
    if (lane < ACT_DIM) {
        const float4* wq = reinterpret_cast<const float4*>(
            Wq + (size_t)lane * HID_DIM + hbase);
        const float4 a0 = __ldg(wq);      // L1-hot across the wave
        const float4 a1 = __ldg(wq + 1);
        const float bqv = (hbase == 0) ? __ldg(bq + lane) : 0.0f;
        #pragma unroll
        for (int i = 0; i < 2; i++) {
            const float qv = bqv
                           + a0.x * hsh[i][0] + a0.y * hsh[i][1]
                           + a0.z * hsh[i][2] + a0.w * hsh[i][3]
                           + a1.x * hsh[i][4] + a1.y * hsh[i][5]
                           + a1.z * hsh[i][6] + a1.w * hsh[i][7];
            atomicAdd(q + (size_t)(b0 + i) * ACT_DIM + lane, qv);
        }
    }
}

extern "C" void kernel_launch(void* const* d_in, const int* in_sizes, int n_in,
                              void* d_out, int out_size) {
    const float* obs = (const float*)d_in[0];  // [1024, 256]
    const float* M   = (const float*)d_in[1];  // [1024, 512, 256]
    const float* W   = (const float*)d_in[2];  // [512, 256]
    const float* bh  = (const float*)d_in[3];  // [512]
    const float* Wq  = (const float*)d_in[4];  // [18, 512]
    const float* bq  = (const float*)d_in[5];  // [18]

    float* q    = (float*)d_out;               // [1024, 18]
    float* newM = q + (size_t)BATCH * ACT_DIM; // [1024, 512, 256]

    // Zero q (atomic accumulation target). Memset node: cheaper than a kernel.
    cudaMemsetAsync(q, 0, (size_t)BATCH * ACT_DIM * sizeof(float));

    dim3 grid(BATCH / 2, HID_DIM / 8);         // batch-major for W reuse
    mpn_step_kernel<<<grid, 256>>>(obs, M, W, bh, Wq, bq, newM, q);
}

// round 12
// speedup vs baseline: 1.0028x; 1.0028x over previous
#include <cuda_runtime.h>

#define OBS_DIM   256
#define HID_DIM   512
#define ACT_DIM   18
#define BATCH     1024
#define ETA       0.01f
#define LAMBDA    0.95f

__device__ __forceinline__ float tanh_approx(float x) {
    float r;
    asm("tanh.approx.f32 %0, %1;" : "=f"(r) : "f"(x));
    return r;
}

// Fused MPN step + Hebbian update + q-head, barrier-free: one (batch, 8
// h-rows) per block, each warp a fully independent load->reduce->store chain
// with NO smem and NO barriers anywhere. After the allreduce every lane holds
// hv, so lanes 0..17 emit this h-row's q contribution directly as one
// predicated RED (hv * Wq[a,h]); Wq is L1-hot (same h for 1024 consecutive
// batch-major blocks). Warps retire immediately after their M stores.
__global__ __launch_bounds__(256) void mpn_step_kernel(
    const float* __restrict__ obs,
    const float* __restrict__ M,
    const float* __restrict__ W,
    const float* __restrict__ bh,
    const float* __restrict__ Wq,
    const float* __restrict__ bq,
    float* __restrict__ newM,
    float* __restrict__ q)
{
    const int b     = blockIdx.x;       // batch-major: W/Wq stay L1-hot
    const int hbase = blockIdx.y * 8;
    const int tid   = threadIdx.x;
    const int warp  = tid >> 5;
    const int lane  = tid & 31;
    const int h     = hbase + warp;

    const float4* xp = reinterpret_cast<const float4*>(obs + (size_t)b * OBS_DIM);
    const float4* wp = reinterpret_cast<const float4*>(W + (size_t)h * OBS_DIM);
    const float4* Mrow = reinterpret_cast<const float4*>(
        M + ((size_t)b * HID_DIM + h) * OBS_DIM);

    // Independent loads, issued back-to-back: M streams (evict-first),
    // W/obs cache-resident.
    const float4 m0 = __ldcs(Mrow + lane);
    const float4 m1 = __ldcs(Mrow + lane + 32);
    const float4 w0 = __ldg(wp + lane);
    const float4 w1 = __ldg(wp + lane + 32);
    const float4 x0 = __ldg(xp + lane);
    const float4 x1 = __ldg(xp + lane + 32);

    // sum_o W[h,o] * obs[b,o] * (1 + M[b,h,o])
    float acc =
        w0.x * x0.x * (1.0f + m0.x) + w0.y * x0.y * (1.0f + m0.y) +
        w0.z * x0.z * (1.0f + m0.z) + w0.w * x0.w * (1.0f + m0.w) +
        w1.x * x1.x * (1.0f + m1.x) + w1.y * x1.y * (1.0f + m1.y) +
        w1.z * x1.z * (1.0f + m1.z) + w1.w * x1.w * (1.0f + m1.w);

    #pragma unroll
    for (int o = 16; o; o >>= 1)
        acc += __shfl_xor_sync(0xffffffffu, acc, o);

    const float hv = tanh_approx(acc + __ldg(bh + h));
    const float eh = ETA * hv;

    float4 n0, n1;
    n0.x = LAMBDA * m0.x + eh * x0.x;  n0.y = LAMBDA * m0.y + eh * x0.y;
    n0.z = LAMBDA * m0.z + eh * x0.z;  n0.w = LAMBDA * m0.w + eh * x0.w;
    n1.x = LAMBDA * m1.x + eh * x1.x;  n1.y = LAMBDA * m1.y + eh * x1.y;
    n1.z = LAMBDA * m1.z + eh * x1.z;  n1.w = LAMBDA * m1.w + eh * x1.w;

    float4* out = reinterpret_cast<float4*>(
        newM + ((size_t)b * HID_DIM + h) * OBS_DIM);
    __stcs(out + lane,      n0);
    __stcs(out + lane + 32, n1);

    // q-head: this warp's own contribution, one predicated RED. Wq column h
    // (18 strided floats) is L1-hot across the batch-major wave.
    if (lane < ACT_DIM) {
        float qv = hv * __ldg(Wq + (size_t)lane * HID_DIM + h);
        if (h == 0) qv += __ldg(bq + lane);   // exact bias fold, once per b
        atomicAdd(q + (size_t)b * ACT_DIM + lane, qv);
    }
}

extern "C" void kernel_launch(void* const* d_in, const int* in_sizes, int n_in,
                              void* d_out, int out_size) {
    const float* obs = (const float*)d_in[0];  // [1024, 256]
    const float* M   = (const float*)d_in[1];  // [1024, 512, 256]
    const float* W   = (const float*)d_in[2];  // [512, 256]
    const float* bh  = (const float*)d_in[3];  // [512]
    const float* Wq  = (const float*)d_in[4];  // [18, 512]
    const float* bq  = (const float*)d_in[5];  // [18]

    float* q    = (float*)d_out;               // [1024, 18]
    float* newM = q + (size_t)BATCH * ACT_DIM; // [1024, 512, 256]

    // Zero q (atomic accumulation target). Memset node: cheaper than a kernel.
    cudaMemsetAsync(q, 0, (size_t)BATCH * ACT_DIM * sizeof(float));

    dim3 grid(BATCH, HID_DIM / 8);             // batch-major for W/Wq reuse
    mpn_step_kernel<<<grid, 256>>>(obs, M, W, bh, Wq, bq, newM, q);
}